// round 1
// baseline (speedup 1.0000x reference)
#include <cuda_runtime.h>
#include <math.h>
#include <cfloat>

#define BB 8
#define QQ 2048
#define GG 128
#define CC 512
#define NT 512
#define NW (NT/32)

// ---------------- device scratch (no allocation allowed) ----------------
__device__ float g_ct[BB*GG*QQ];   // transposed cost: CT[b][g][q]  (8 MB)
__device__ int   g_labels[BB*GG];
__device__ int   g_na[BB];

// ---------------- prep: normalize int inputs (int32 vs int64 on disk) ----
__global__ void prep_kernel(const int* __restrict__ lab_raw,
                            const int* __restrict__ na_raw) {
    __shared__ int nzl, nzn;
    int t = threadIdx.x;
    if (t == 0) { nzl = 0; nzn = 0; }
    __syncthreads();
    // Only probe the first half of the element count so an int32 buffer is
    // never read out of bounds. Values are in [0,512)/[1,128], so for int64
    // data every probed high word is 0; for int32 data the probed words are
    // independent labels/counts (all-zero probability ~0).
    for (int k = t; k < (BB*GG)/2; k += blockDim.x)
        if (lab_raw[2*k+1] != 0) atomicExch(&nzl, 1);
    for (int k = t; k < BB/2; k += blockDim.x)
        if (na_raw[2*k+1] != 0) atomicExch(&nzn, 1);
    __syncthreads();
    bool l64 = (nzl == 0), n64 = (nzn == 0);
    for (int k = t; k < BB*GG; k += blockDim.x)
        g_labels[k] = l64 ? lab_raw[2*k] : lab_raw[k];
    if (t < BB)
        g_na[t] = n64 ? na_raw[2*t] : na_raw[t];
}

// ---------------- cost: focal-class gather + weighted sum ---------------
__global__ void cost_kernel(const float* __restrict__ sem,
                            const float* __restrict__ center,
                            const float* __restrict__ sizes,
                            const float* __restrict__ gious,
                            float* __restrict__ fc) {
    int q = blockIdx.x, b = blockIdx.y, g = threadIdx.x;
    int lab = g_labels[b*GG + g];
    float s = sem[((size_t)(b*QQ + q))*CC + lab];
    // XLA lowers lax.logistic as 0.5 + 0.5*tanh(0.5*x)
    float p = 0.5f + 0.5f * tanhf(0.5f * s);
    float pos = 0.25f * (1.0f - p) * (1.0f - p) * (-logf(p + 1e-8f));
    float neg = 0.75f * p * p * (-log1pf(-(p - 1e-8f)));
    float diff = pos - neg;
    size_t idx = ((size_t)(b*QQ + q))*GG + g;
    fc[idx] = 2.0f*diff + 5.0f*center[idx] + 1.0f*sizes[idx] - 2.0f*gious[idx];
}

// ---------------- transpose fc[b][q][g] -> CT[b][g][q] ------------------
__global__ void transpose_kernel(const float* __restrict__ fc) {
    __shared__ float tile[32][33];
    int b = blockIdx.z;
    int q0 = blockIdx.x * 32, g0 = blockIdx.y * 32;
    int x = threadIdx.x;
    for (int r = threadIdx.y; r < 32; r += 8)
        tile[r][x] = fc[((size_t)(b*QQ + q0 + r))*GG + g0 + x];
    __syncthreads();
    for (int r = threadIdx.y; r < 32; r += 8)
        g_ct[((size_t)(b*GG + g0 + r))*QQ + q0 + x] = tile[x][r];
}

// ---------------- LSA: exact replica of the reference's algorithm -------
// NOTE: the reference _lsa never writes minv1/way1 back, so it is NOT true
// JV. Per row i: repeatedly argmin current row's reduced cost over free
// columns (float64, first-index tie-break), update u over p[used] and v over
// used, hop to the matched row; assign the final unmatched column to row i.
__global__ void __launch_bounds__(NT) lsa_kernel(float* __restrict__ out_inds,
                                                 float* __restrict__ out_mask) {
    __shared__ double v[QQ + 1];
    __shared__ double u[GG + 1];
    __shared__ unsigned char used[QQ + 1];
    __shared__ short p[QQ + 1];
    __shared__ unsigned short ulist[QQ + 1];
    __shared__ double sbest[NW];
    __shared__ int sbj[NW];
    __shared__ int s_j0, s_i0, s_cnt, s_jmin, s_done;
    __shared__ double s_delta;

    int b = blockIdx.x;
    int tid = threadIdx.x;
    int lane = tid & 31, wid = tid >> 5;
    const float* CT = g_ct + (size_t)b * GG * QQ;

    int na = g_na[b];
    if (na < 0) na = 0;
    if (na > GG) na = GG;

    for (int j = tid; j <= QQ; j += NT) { v[j] = 0.0; p[j] = 0; }
    for (int j = tid; j <= GG; j += NT) u[j] = 0.0;
    __syncthreads();

    for (int i = 1; i <= na; i++) {
        for (int j = tid; j <= QQ; j += NT) used[j] = 0;
        if (tid == 0) { p[0] = (short)i; s_j0 = 0; s_cnt = 0; }
        __syncthreads();

        while (true) {
            if (tid == 0) {
                int j0 = s_j0;
                used[j0] = 1;
                ulist[s_cnt] = (unsigned short)j0;
                s_cnt = s_cnt + 1;
                s_i0 = p[j0];
            }
            __syncthreads();                    // used/i0 visible

            int i0 = s_i0;
            const float* row = CT + (size_t)(i0 - 1) * QQ;
            double ui = u[i0];

            double best = DBL_MAX;
            int bj = 0x7fffffff;
            #pragma unroll
            for (int k = 0; k < QQ / NT; k++) {
                int j = tid + 1 + k * NT;
                if (!used[j]) {
                    double cur = ((double)row[j - 1] - ui) - v[j];
                    if (cur < best) { best = cur; bj = j; }   // ascending j => first-index tie-break
                }
            }
            // warp reduce (lexicographic (val, j) min — matches np.argmin)
            #pragma unroll
            for (int off = 16; off > 0; off >>= 1) {
                double ob = __shfl_down_sync(0xffffffffu, best, off);
                int    oj = __shfl_down_sync(0xffffffffu, bj,   off);
                if (ob < best || (ob == best && oj < bj)) { best = ob; bj = oj; }
            }
            if (lane == 0) { sbest[wid] = best; sbj[wid] = bj; }
            __syncthreads();
            if (wid == 0) {
                best = (lane < NW) ? sbest[lane] : DBL_MAX;
                bj   = (lane < NW) ? sbj[lane]   : 0x7fffffff;
                #pragma unroll
                for (int off = NW / 2; off > 0; off >>= 1) {
                    double ob = __shfl_down_sync(0xffffffffu, best, off);
                    int    oj = __shfl_down_sync(0xffffffffu, bj,   off);
                    if (ob < best || (ob == best && oj < bj)) { best = ob; bj = oj; }
                }
                if (lane == 0) { s_delta = best; s_jmin = bj; }
            }
            __syncthreads();                    // delta/jmin visible; scans done

            int cnt = s_cnt;
            double delta = s_delta;
            for (int k = tid; k < cnt; k += NT) {
                int jj = ulist[k];
                u[p[jj]] += delta;              // p over used cols is duplicate-free
                v[jj]    -= delta;
            }
            if (tid == 0) {
                s_j0 = s_jmin;
                s_done = (p[s_jmin] == 0);
            }
            __syncthreads();                    // u/v updates + done flag visible
            if (s_done) break;
        }
        if (tid == 0) p[s_j0] = (short)i;       // way==0 => single-step backtrack
        __syncthreads();
    }

    // outputs: proposal j-1 matched to gt p[j]-1
    for (int j = tid + 1; j <= QQ; j += NT) {
        int pj = p[j];
        size_t o = (size_t)b * QQ + (j - 1);
        out_inds[o] = (pj > 0) ? (float)(pj - 1) : 0.0f;
        out_mask[o] = (pj > 0) ? 1.0f : 0.0f;
    }
}

// ---------------- launch ------------------------------------------------
extern "C" void kernel_launch(void* const* d_in, const int* in_sizes, int n_in,
                              void* d_out, int out_size) {
    const float* sem    = (const float*)d_in[0];
    const float* center = (const float*)d_in[1];
    const float* sizes  = (const float*)d_in[2];
    const float* gious  = (const float*)d_in[3];
    const int*   labels = (const int*)d_in[4];
    const int*   na     = (const int*)d_in[5];

    float* out      = (float*)d_out;
    float* out_inds = out;
    float* out_mask = out + (size_t)BB * QQ;
    float* fc       = out + (size_t)2 * BB * QQ;   // final_cost region

    prep_kernel<<<1, 512>>>(labels, na);
    cost_kernel<<<dim3(QQ, BB), GG>>>(sem, center, sizes, gious, fc);
    transpose_kernel<<<dim3(QQ/32, GG/32, BB), dim3(32, 8)>>>(fc);
    lsa_kernel<<<BB, NT>>>(out_inds, out_mask);
}

// round 2
// speedup vs baseline: 3.4061x; 3.4061x over previous
#include <cuda_runtime.h>
#include <math.h>
#include <cfloat>

#define BB 8
#define QQ 2048
#define GG 128
#define CC 512
#define NT 512
#define NW (NT/32)
#define MAXC 128

// ---------------- device scratch (no allocation allowed) ----------------
__device__ float g_ct[BB*GG*QQ];   // transposed cost: CT[b][g][q]  (8 MB)
__device__ int   g_labels[BB*GG];
__device__ int   g_na[BB];

// ---------------- prep: normalize int inputs (int32 vs int64 on disk) ----
__global__ void prep_kernel(const int* __restrict__ lab_raw,
                            const int* __restrict__ na_raw) {
    __shared__ int nzl, nzn;
    int t = threadIdx.x;
    if (t == 0) { nzl = 0; nzn = 0; }
    __syncthreads();
    for (int k = t; k < (BB*GG)/2; k += blockDim.x)
        if (lab_raw[2*k+1] != 0) atomicExch(&nzl, 1);
    for (int k = t; k < BB/2; k += blockDim.x)
        if (na_raw[2*k+1] != 0) atomicExch(&nzn, 1);
    __syncthreads();
    bool l64 = (nzl == 0), n64 = (nzn == 0);
    for (int k = t; k < BB*GG; k += blockDim.x)
        g_labels[k] = l64 ? lab_raw[2*k] : lab_raw[k];
    if (t < BB)
        g_na[t] = n64 ? na_raw[2*t] : na_raw[t];
}

// ---------------- cost: focal-class gather + weighted sum ---------------
__global__ void cost_kernel(const float* __restrict__ sem,
                            const float* __restrict__ center,
                            const float* __restrict__ sizes,
                            const float* __restrict__ gious,
                            float* __restrict__ fc) {
    int q = blockIdx.x, b = blockIdx.y, g = threadIdx.x;
    int lab = g_labels[b*GG + g];
    float s = sem[((size_t)(b*QQ + q))*CC + lab];
    // XLA lowers lax.logistic as 0.5 + 0.5*tanh(0.5*x)
    float p = 0.5f + 0.5f * tanhf(0.5f * s);
    float pos = 0.25f * (1.0f - p) * (1.0f - p) * (-logf(p + 1e-8f));
    float neg = 0.75f * p * p * (-log1pf(-(p - 1e-8f)));
    float diff = pos - neg;
    size_t idx = ((size_t)(b*QQ + q))*GG + g;
    fc[idx] = 2.0f*diff + 5.0f*center[idx] + 1.0f*sizes[idx] - 2.0f*gious[idx];
}

// ---------------- transpose fc[b][q][g] -> CT[b][g][q] ------------------
__global__ void transpose_kernel(const float* __restrict__ fc) {
    __shared__ float tile[32][33];
    int b = blockIdx.z;
    int q0 = blockIdx.x * 32, g0 = blockIdx.y * 32;
    int x = threadIdx.x;
    for (int r = threadIdx.y; r < 32; r += 8)
        tile[r][x] = fc[((size_t)(b*QQ + q0 + r))*GG + g0 + x];
    __syncthreads();
    for (int r = threadIdx.y; r < 32; r += 8)
        g_ct[((size_t)(b*GG + g0 + r))*QQ + q0 + x] = tile[x][r];
}

// --------- order-preserving uint key for float (monotone) ---------------
__device__ __forceinline__ unsigned fkey(float f) {
    unsigned u = __float_as_uint(f);
    return (u & 0x80000000u) ? ~u : (u | 0x80000000u);
}
__device__ __forceinline__ float finv(unsigned k) {
    unsigned u = (k & 0x80000000u) ? (k & 0x7fffffffu) : ~k;
    return __uint_as_float(u);
}

// ---------------- LSA: exact replica of the reference's algorithm -------
// fp32 pre-scan + fp64 verification of eps-candidates; used-columns are
// excluded via a -FLT_MAX sentinel in the fp32 shadow of v (cur32 -> +inf),
// restored from the fp64 master when the row's search ends.
__global__ void __launch_bounds__(NT) lsa_kernel(float* __restrict__ out_inds,
                                                 float* __restrict__ out_mask) {
    __shared__ double v[QQ + 1];        // fp64 master potentials
    __shared__ float  vf[QQ + 1];       // fp32 shadow (sentinel = -FLT_MAX when used)
    __shared__ double u[GG + 1];
    __shared__ short  p[QQ + 1];
    __shared__ unsigned short ulist[QQ + 1];
    __shared__ double cand_v[MAXC];
    __shared__ int    cand_j[MAXC];
    __shared__ int s_ncand, s_done, s_i0;
    __shared__ unsigned s_key;
    __shared__ double s_ui;
    __shared__ float  s_uif;

    int b = blockIdx.x;
    int tid = threadIdx.x;
    int lane = tid & 31;
    const float* CT = g_ct + (size_t)b * GG * QQ;

    int na = g_na[b];
    if (na < 0) na = 0;
    if (na > GG) na = GG;

    for (int j = tid; j <= QQ; j += NT) { v[j] = 0.0; vf[j] = 0.0f; p[j] = 0; }
    for (int j = tid; j <= GG; j += NT) u[j] = 0.0;
    __syncthreads();

    int cnt = 0;   // meaningful only on tid 0 (path length incl. dummy col 0)

    for (int i = 1; i <= na; i++) {
        if (tid == 0) {
            p[0] = (short)i;
            ulist[0] = 0; cnt = 1;           // column 0 is "used" first
            s_i0 = i;
            s_ui = u[i];                     // == 0 for a fresh row, read anyway
            s_uif = (float)s_ui;
            s_ncand = 0;
            s_key = 0xffffffffu;
        }
        __syncthreads();                     // (1) setup visible

        while (true) {
            // ---- pass 1: fp32 scan, block min via shared atomicMin ----
            const float* row = CT + (size_t)(s_i0 - 1) * QQ;
            float uif = s_uif;
            float c0, c1, c2, c3;
            {
                int j = tid + 1;
                c0 = (row[j - 1]          - uif) - vf[j];
                c1 = (row[j - 1 + NT]     - uif) - vf[j + NT];
                c2 = (row[j - 1 + 2*NT]   - uif) - vf[j + 2*NT];
                c3 = (row[j - 1 + 3*NT]   - uif) - vf[j + 3*NT];
            }
            float m = fminf(fminf(c0, c1), fminf(c2, c3));
            #pragma unroll
            for (int off = 16; off > 0; off >>= 1)
                m = fminf(m, __shfl_down_sync(0xffffffffu, m, off));
            if (lane == 0) atomicMin(&s_key, fkey(m));
            __syncthreads();                 // (2) min32 ready

            // ---- pass 2: post eps-candidates with exact fp64 value ----
            float thr = finv(s_key) + 1e-3f;
            double uid = s_ui;
            if (c0 <= thr) {
                int j = tid + 1;
                double cd = ((double)row[j - 1] - uid) - v[j];
                int slot = atomicAdd(&s_ncand, 1);
                if (slot < MAXC) { cand_v[slot] = cd; cand_j[slot] = j; }
            }
            if (c1 <= thr) {
                int j = tid + 1 + NT;
                double cd = ((double)row[j - 1] - uid) - v[j];
                int slot = atomicAdd(&s_ncand, 1);
                if (slot < MAXC) { cand_v[slot] = cd; cand_j[slot] = j; }
            }
            if (c2 <= thr) {
                int j = tid + 1 + 2*NT;
                double cd = ((double)row[j - 1] - uid) - v[j];
                int slot = atomicAdd(&s_ncand, 1);
                if (slot < MAXC) { cand_v[slot] = cd; cand_j[slot] = j; }
            }
            if (c3 <= thr) {
                int j = tid + 1 + 3*NT;
                double cd = ((double)row[j - 1] - uid) - v[j];
                int slot = atomicAdd(&s_ncand, 1);
                if (slot < MAXC) { cand_v[slot] = cd; cand_j[slot] = j; }
            }
            __syncthreads();                 // (3) candidates posted

            // ---- tid0 serial: exact argmin, delta apply, next setup ----
            if (tid == 0) {
                int nc = s_ncand; if (nc > MAXC) nc = MAXC;
                double best = DBL_MAX; int bj = 0x7fffffff;
                for (int s = 0; s < nc; s++) {
                    double cv = cand_v[s]; int cj = cand_j[s];
                    if (cv < best || (cv == best && cj < bj)) { best = cv; bj = cj; }
                }
                double delta = best;
                for (int k = 0; k < cnt; k++) {     // path columns (incl. 0)
                    int jj = ulist[k];
                    u[p[jj]] += delta;
                    v[jj]    -= delta;
                }
                if (p[bj] == 0) {
                    p[bj] = (short)i;               // way==0 single-step backtrack
                    for (int k = 1; k < cnt; k++) { // restore fp32 shadow
                        int jj = ulist[k];
                        vf[jj] = (float)v[jj];
                    }
                    s_done = 1;
                } else {
                    int i0 = p[bj];
                    s_i0 = i0;
                    s_ui = u[i0];                   // after delta apply
                    s_uif = (float)u[i0];
                    vf[bj] = -FLT_MAX;              // mark used
                    ulist[cnt++] = (unsigned short)bj;
                    s_ncand = 0;
                    s_key = 0xffffffffu;
                    s_done = 0;
                }
            }
            __syncthreads();                 // (4) == (1) of next iteration
            if (s_done) break;
        }
    }

    // outputs: proposal j-1 matched to gt p[j]-1
    for (int j = tid + 1; j <= QQ; j += NT) {
        int pj = p[j];
        size_t o = (size_t)b * QQ + (j - 1);
        out_inds[o] = (pj > 0) ? (float)(pj - 1) : 0.0f;
        out_mask[o] = (pj > 0) ? 1.0f : 0.0f;
    }
}

// ---------------- launch ------------------------------------------------
extern "C" void kernel_launch(void* const* d_in, const int* in_sizes, int n_in,
                              void* d_out, int out_size) {
    const float* sem    = (const float*)d_in[0];
    const float* center = (const float*)d_in[1];
    const float* sizes  = (const float*)d_in[2];
    const float* gious  = (const float*)d_in[3];
    const int*   labels = (const int*)d_in[4];
    const int*   na     = (const int*)d_in[5];

    float* out      = (float*)d_out;
    float* out_inds = out;
    float* out_mask = out + (size_t)BB * QQ;
    float* fc       = out + (size_t)2 * BB * QQ;   // final_cost region

    prep_kernel<<<1, 512>>>(labels, na);
    cost_kernel<<<dim3(QQ, BB), GG>>>(sem, center, sizes, gious, fc);
    transpose_kernel<<<dim3(QQ/32, GG/32, BB), dim3(32, 8)>>>(fc);
    lsa_kernel<<<BB, NT>>>(out_inds, out_mask);
}